// round 1
// baseline (speedup 1.0000x reference)
#include <cuda_runtime.h>
#include <cuda_bf16.h>

// YOLOv3 head decode.
// Input layout (per level): out[b, c, h, w], c = 3 + a*85 + f  (first 3 channels = iou-pred per anchor)
// Output: boxes [B, 22743, 4] followed by scores [B, 22743, 80] (float32).
//
// Strategy:
//  - warp = one anchor, lane = one spatial position  -> every channel load is a
//    contiguous 128B warp transaction (pos is the fastest-varying input dim).
//  - scores/boxes staged in shared memory (row stride 81 -> conflict-free
//    compute-phase stores since gcd(3*81,32)=1), then written out with fully
//    coalesced float4 stores.

#define NC 80
#define ROWS_TOT 22743   // (361 + 1444 + 5776) * 3

__device__ __forceinline__ float sig(float x) {
    float e = __expf(-x);
    return __fdividef(1.0f, 1.0f + e);
}

__global__ __launch_bounds__(96) void yolo_decode_kernel(
    const float* __restrict__ in,      // [B, 258, H, W]
    const float* __restrict__ im_size, // [B, 2]  (h, w)
    float* __restrict__ out,           // boxes then scores
    int B, int H, int W, float stride,
    float aw0, float ah0, float aw1, float ah1, float aw2, float ah2,
    int row_off)                       // level row offset into the 22743 rows
{
    __shared__ float s_scores[96 * 81]; // 96 rows x 80 cols, stride 81 (conflict-free)
    __shared__ float s_boxes[96 * 4];

    const int HW    = H * W;
    const int a     = threadIdx.x >> 5;   // anchor = warp id (0..2)
    const int pin   = threadIdx.x & 31;   // position-in-chunk = lane
    const int chunk = blockIdx.x;
    const int b     = blockIdx.y;
    const int pos   = chunk * 32 + pin;

    if (pos < HW) {
        const float* base = in + ((long)b * 258) * HW + pos;

        // iou-pred for this anchor
        float ip = sig(base[a * HW]);

        const int c0 = 3 + a * 85;
        const float* pc = base + (long)c0 * HW;

        float dx = pc[0];
        float dy = pc[1 * HW];
        float dw = pc[2 * HW];
        float dh = pc[3 * HW];
        float to = pc[4 * HW];

        float obj  = sig(to);
        // conf = sigmoid(de_sigmoid(obj^0.6 * ip^0.4)) == obj^0.6 * ip^0.4 (clip is a no-op here)
        float conf = __expf(0.6f * __logf(obj) + 0.4f * __logf(ip));

        int w_ = pos % W;
        int h_ = pos / W;
        const float half_off = (1.05f - 1.0f) * 0.5f;
        float x = (1.05f * sig(dx) + (float)w_ - half_off) * stride;
        float y = (1.05f * sig(dy) + (float)h_ - half_off) * stride;

        float aw = (a == 0) ? aw0 : (a == 1) ? aw1 : aw2;
        float ah = (a == 0) ? ah0 : (a == 1) ? ah1 : ah2;
        float bw = __expf(dw) * aw;
        float bh = __expf(dh) * ah;

        float imh = im_size[2 * b + 0];
        float imw = im_size[2 * b + 1];
        float inv = __fdividef(1.0f, (float)H * stride);
        float sx = imw * inv;
        float sy = imh * inv;

        float x0 = (x - 0.5f * bw) * sx; if (x0 < 0.0f)  x0 = 0.0f;
        float y0 = (y - 0.5f * bh) * sy; if (y0 < 0.0f)  y0 = 0.0f;
        float x1 = (x + 0.5f * bw) * sx; if (x1 > imw)   x1 = imw;
        float y1 = (y + 0.5f * bh) * sy; if (y1 > imh)   y1 = imh;

        const int lrow = pin * 3 + a;      // local row within block (0..95)
        float* sb = s_boxes + lrow * 4;
        sb[0] = x0; sb[1] = y0; sb[2] = x1; sb[3] = y1;

        float* ss = s_scores + lrow * 81;  // lane stride 243 floats -> conflict-free
        const float* pp = pc + 5 * HW;
        #pragma unroll 10
        for (int c = 0; c < NC; c++) {
            ss[c] = conf * sig(pp[c * HW]);
        }
    }
    __syncthreads();

    // valid rows for this block (tail chunk may be partial)
    int npos = HW - chunk * 32;
    if (npos > 32) npos = 32;
    const int nrows = npos * 3;
    const int grow0 = row_off + chunk * 96;   // first global row this block owns

    // boxes: coalesced float4 per row
    if ((int)threadIdx.x < nrows) {
        float4* dst = (float4*)(out + ((long)b * ROWS_TOT + grow0 + threadIdx.x) * 4);
        *dst = *(float4*)(s_boxes + threadIdx.x * 4);
    }

    // scores: contiguous block of nrows*80 floats, coalesced float4 stores
    const long boxes_tot = (long)B * ROWS_TOT * 4;
    float* sbase = out + boxes_tot + ((long)b * ROWS_TOT + grow0) * (long)NC;
    const int n = nrows * NC;
    for (int j = (int)threadIdx.x * 4; j < n; j += 96 * 4) {
        int row = j / NC;
        int col = j - row * NC;           // multiple of 4 (4 | 80)
        const float* sp = s_scores + row * 81 + col;
        float4 v = make_float4(sp[0], sp[1], sp[2], sp[3]);
        *(float4*)(sbase + j) = v;
    }
}

extern "C" void kernel_launch(void* const* d_in, const int* in_sizes, int n_in,
                              void* d_out, int out_size) {
    (void)n_in; (void)out_size;
    const float* out0 = (const float*)d_in[0]; // [B, 258, 19, 19]
    const float* out1 = (const float*)d_in[1]; // [B, 258, 38, 38]
    const float* out2 = (const float*)d_in[2]; // [B, 258, 76, 76]
    const float* imsz = (const float*)d_in[3]; // [B, 2]
    float* o = (float*)d_out;

    const int B = in_sizes[3] / 2;

    // level 0: 19x19, stride 32, rows [0, 1083)
    yolo_decode_kernel<<<dim3((19 * 19 + 31) / 32, B), 96>>>(
        out0, imsz, o, B, 19, 19, 32.0f,
        116.0f, 90.0f, 156.0f, 198.0f, 373.0f, 326.0f, 0);
    // level 1: 38x38, stride 16, rows [1083, 5415)
    yolo_decode_kernel<<<dim3((38 * 38 + 31) / 32, B), 96>>>(
        out1, imsz, o, B, 38, 38, 16.0f,
        30.0f, 61.0f, 62.0f, 45.0f, 59.0f, 119.0f, 1083);
    // level 2: 76x76, stride 8, rows [5415, 22743)
    yolo_decode_kernel<<<dim3((76 * 76 + 31) / 32, B), 96>>>(
        out2, imsz, o, B, 76, 76, 8.0f,
        10.0f, 13.0f, 16.0f, 30.0f, 33.0f, 23.0f, 5415);
}

// round 4
// speedup vs baseline: 1.0483x; 1.0483x over previous
#include <cuda_runtime.h>
#include <cuda_bf16.h>

// YOLOv3 head decode — fused single-launch version.
// Input per level: [B, 258, H, W], channel c = 3 + a*85 + f (first 3 = iou-pred per anchor).
// Output: boxes [B, 22743, 4] then scores [B, 22743, 80] (float32).
//
// warp = anchor, lane = spatial position -> coalesced 128B input transactions.
// Scores staged through a double-buffered 20-channel smem tile (row stride 21 ->
// lane stride 63, conflict-free), written out with coalesced float4 stores.

#define NC 80
#define TILE 20
#define NTILES 4
#define SROW (TILE + 1)
#define ROWS_TOT 22743     // (361 + 1444 + 5776) * 3
#define CHUNKS_TOT 239     // 12 + 46 + 181

__constant__ int   c_HW[3]     = {361, 1444, 5776};
__constant__ int   c_W[3]      = {19, 38, 76};
__constant__ int   c_chunk0[3] = {0, 12, 58};
__constant__ int   c_rowoff[3] = {0, 1083, 5415};
__constant__ float c_stride[3] = {32.0f, 16.0f, 8.0f};
__constant__ float c_aw[3][3]  = {{116.f,156.f,373.f},{30.f,62.f,59.f},{10.f,16.f,33.f}};
__constant__ float c_ah[3][3]  = {{90.f,198.f,326.f},{61.f,45.f,119.f},{13.f,30.f,23.f}};

__device__ __forceinline__ float sig(float x) {
    return __fdividef(1.0f, 1.0f + __expf(-x));
}

__global__ __launch_bounds__(96, 12) void yolo_fused(
    const float* __restrict__ in0, const float* __restrict__ in1,
    const float* __restrict__ in2, const float* __restrict__ imsz,
    float* __restrict__ out, int B)
{
    __shared__ float s_scores[2][96 * SROW];   // 15.75 KB

    const int bid = blockIdx.x;
    const int b   = bid / CHUNKS_TOT;
    const int t   = bid - b * CHUNKS_TOT;

    int level; const float* in;
    if (t < 12)      { level = 0; in = in0; }
    else if (t < 58) { level = 1; in = in1; }
    else             { level = 2; in = in2; }

    const int   chunk  = t - c_chunk0[level];
    const int   HW     = c_HW[level];
    const int   W      = c_W[level];
    const float stride = c_stride[level];

    const int a    = threadIdx.x >> 5;   // anchor = warp
    const int pin  = threadIdx.x & 31;   // position-in-chunk = lane
    const int pos  = chunk * 32 + pin;
    const bool valid = pos < HW;
    const int lrow = pin * 3 + a;        // local output row (0..95)

    int npos = HW - chunk * 32; if (npos > 32) npos = 32;
    const int nrows = npos * 3;
    const int grow0 = c_rowoff[level] + chunk * 96;

    float conf = 0.0f;
    const float* pp = in;
    if (valid) {
        const float* base = in + (long)b * 258 * HW + pos;
        float ip = sig(base[a * HW]);

        const float* pc = base + (3 + a * 85) * HW;
        float dx = pc[0];
        float dy = pc[HW];
        float dw = pc[2 * HW];
        float dh = pc[3 * HW];
        float to = pc[4 * HW];
        pp = pc + 5 * HW;

        float obj = sig(to);
        // sigmoid(de_sigmoid(obj^0.6 * ip^0.4)) == obj^0.6 * ip^0.4 (clips are no-ops for N(0,1) logits)
        conf = __expf(0.6f * __logf(obj) + 0.4f * __logf(ip));

        int h_ = pos / W;
        int w_ = pos - h_ * W;
        float x = (1.05f * sig(dx) + (float)w_ - 0.025f) * stride;
        float y = (1.05f * sig(dy) + (float)h_ - 0.025f) * stride;
        float bw = __expf(dw) * c_aw[level][a];
        float bh = __expf(dh) * c_ah[level][a];

        float imh = imsz[2 * b];
        float imw = imsz[2 * b + 1];
        float inv = __fdividef(1.0f, (float)W * stride);   // = 1/608
        float sx = imw * inv, sy = imh * inv;

        float x0 = (x - 0.5f * bw) * sx; x0 = fmaxf(x0, 0.0f);
        float y0 = (y - 0.5f * bh) * sy; y0 = fmaxf(y0, 0.0f);
        float x1 = (x + 0.5f * bw) * sx; x1 = fminf(x1, imw);
        float y1 = (y + 0.5f * bh) * sy; y1 = fminf(y1, imh);

        // boxes: direct store (5% of traffic; imperfect coalescing is fine)
        *(float4*)(out + ((long)b * ROWS_TOT + grow0 + lrow) * 4) =
            make_float4(x0, y0, x1, y1);
    }

    // scores: 4 channel-tiles of 20, double-buffered -> one barrier per tile.
    // WAR safety: tile k+2 reuses buf[k&1]; the barrier inside tile k+1
    // guarantees all consumers of tile k finished before tile k+2 is produced.
    float* sbase = out + (long)B * ROWS_TOT * 4 + ((long)b * ROWS_TOT + grow0) * NC;
    float* srow  = s_scores[0] + lrow * SROW;

    for (int tile = 0; tile < NTILES; tile++) {
        float* buf = s_scores[tile & 1];
        if (valid) {
            const float* p = pp + tile * TILE * HW;
            float* ss = srow + (tile & 1) * (96 * SROW);
            #pragma unroll
            for (int c = 0; c < TILE; c++)
                ss[c] = conf * sig(p[c * HW]);
        }
        __syncthreads();

        const int nfl = nrows * TILE;
        float* obase = sbase + tile * TILE;
        for (int j = (int)threadIdx.x * 4; j < nfl; j += 96 * 4) {
            int row = j / TILE;
            int col = j - row * TILE;        // multiple of 4 (4 | 20)
            const float* sp = buf + row * SROW + col;
            *(float4*)(obase + (long)row * NC + col) =
                make_float4(sp[0], sp[1], sp[2], sp[3]);
        }
    }
}

extern "C" void kernel_launch(void* const* d_in, const int* in_sizes, int n_in,
                              void* d_out, int out_size) {
    (void)n_in; (void)out_size;
    const float* out0 = (const float*)d_in[0]; // [B, 258, 19, 19]
    const float* out1 = (const float*)d_in[1]; // [B, 258, 38, 38]
    const float* out2 = (const float*)d_in[2]; // [B, 258, 76, 76]
    const float* imsz = (const float*)d_in[3]; // [B, 2]
    float* o = (float*)d_out;

    const int B = in_sizes[3] / 2;
    yolo_fused<<<CHUNKS_TOT * B, 96>>>(out0, out1, out2, imsz, o, B);
}

// round 6
// speedup vs baseline: 1.4721x; 1.4043x over previous
#include <cuda_runtime.h>
#include <cuda_bf16.h>

// YOLOv3 head decode — fused single launch, MLP-batched score loads.
// Input per level: [B, 258, H, W], channel c = 3 + a*85 + f (first 3 = iou-pred per anchor).
// Output: boxes [B, 22743, 4] then scores [B, 22743, 80] (float32).
//
// warp = anchor, lane = spatial position -> coalesced 128B input transactions.
// Score channels processed in 5 tiles of 16: each tile first batches 16
// independent LDGs into registers (explicit MLP=16 -> ~2KB/warp in flight),
// then computes sigmoids into a double-buffered smem tile (row stride 17 ->
// lane stride 51, conflict-free), then writes out coalesced float4 stores.

#define NC 80
#define TILE 16
#define NTILES 5
#define SROW (TILE + 1)
#define ROWS_TOT 22743     // (361 + 1444 + 5776) * 3
#define CHUNKS_TOT 239     // 12 + 46 + 181

__constant__ int   c_HW[3]     = {361, 1444, 5776};
__constant__ int   c_W[3]      = {19, 38, 76};
__constant__ int   c_chunk0[3] = {0, 12, 58};
__constant__ int   c_rowoff[3] = {0, 1083, 5415};
__constant__ float c_stride[3] = {32.0f, 16.0f, 8.0f};
__constant__ float c_aw[3][3]  = {{116.f,156.f,373.f},{30.f,62.f,59.f},{10.f,16.f,33.f}};
__constant__ float c_ah[3][3]  = {{90.f,198.f,326.f},{61.f,45.f,119.f},{13.f,30.f,23.f}};

__device__ __forceinline__ float sig(float x) {
    return __fdividef(1.0f, 1.0f + __expf(-x));
}

__global__ __launch_bounds__(96, 12) void yolo_fused(
    const float* __restrict__ in0, const float* __restrict__ in1,
    const float* __restrict__ in2, const float* __restrict__ imsz,
    float* __restrict__ out, int B)
{
    __shared__ float s_scores[2][96 * SROW];   // 13.3 KB

    const int bid = blockIdx.x;
    const int b   = bid / CHUNKS_TOT;
    const int t   = bid - b * CHUNKS_TOT;

    int level; const float* in;
    if (t < 12)      { level = 0; in = in0; }
    else if (t < 58) { level = 1; in = in1; }
    else             { level = 2; in = in2; }

    const int   chunk  = t - c_chunk0[level];
    const int   HW     = c_HW[level];
    const int   W      = c_W[level];
    const float stride = c_stride[level];

    const int a    = threadIdx.x >> 5;   // anchor = warp
    const int pin  = threadIdx.x & 31;   // position-in-chunk = lane
    const int pos  = chunk * 32 + pin;
    const bool valid = pos < HW;
    const int lrow = pin * 3 + a;        // local output row (0..95)

    int npos = HW - chunk * 32; if (npos > 32) npos = 32;
    const int nrows = npos * 3;
    const int grow0 = c_rowoff[level] + chunk * 96;

    float conf = 0.0f;
    const float* pp = in;
    if (valid) {
        const float* base = in + (long)b * 258 * HW + pos;

        // batch the 6 header loads before any MUFU math
        float ri = base[a * HW];
        const float* pc = base + (3 + a * 85) * HW;
        float dx = pc[0];
        float dy = pc[HW];
        float dw = pc[2 * HW];
        float dh = pc[3 * HW];
        float to = pc[4 * HW];
        pp = pc + 5 * HW;

        float ip  = sig(ri);
        float obj = sig(to);
        // sigmoid(de_sigmoid(obj^0.6 * ip^0.4)) == obj^0.6 * ip^0.4 (clips are no-ops for N(0,1) logits)
        conf = __expf(0.6f * __logf(obj) + 0.4f * __logf(ip));

        int h_ = pos / W;
        int w_ = pos - h_ * W;
        float x = (1.05f * sig(dx) + (float)w_ - 0.025f) * stride;
        float y = (1.05f * sig(dy) + (float)h_ - 0.025f) * stride;
        float bw = __expf(dw) * c_aw[level][a];
        float bh = __expf(dh) * c_ah[level][a];

        float imh = imsz[2 * b];
        float imw = imsz[2 * b + 1];
        float inv = __fdividef(1.0f, (float)W * stride);   // = 1/608
        float sx = imw * inv, sy = imh * inv;

        float x0 = (x - 0.5f * bw) * sx; x0 = fmaxf(x0, 0.0f);
        float y0 = (y - 0.5f * bh) * sy; y0 = fmaxf(y0, 0.0f);
        float x1 = (x + 0.5f * bw) * sx; x1 = fminf(x1, imw);
        float y1 = (y + 0.5f * bh) * sy; y1 = fminf(y1, imh);

        // boxes: direct store (5% of traffic)
        *(float4*)(out + ((long)b * ROWS_TOT + grow0 + lrow) * 4) =
            make_float4(x0, y0, x1, y1);
    }

    // scores: 5 channel-tiles of 16, double-buffered -> one barrier per tile.
    // WAR safety: tile k+2 reuses buf[k&1]; the barrier inside tile k+1
    // guarantees all consumers of tile k finished before tile k+2 is produced.
    float* sbase = out + (long)B * ROWS_TOT * 4 + ((long)b * ROWS_TOT + grow0) * NC;
    float* srow  = s_scores[0] + lrow * SROW;

    for (int tile = 0; tile < NTILES; tile++) {
        float* buf = s_scores[tile & 1];
        if (valid) {
            const float* p = pp + tile * (TILE * HW);
            // phase 1: 16 independent loads, no consumers -> front-batched MLP
            float v[TILE];
            #pragma unroll
            for (int c = 0; c < TILE; c++)
                v[c] = p[c * HW];
            // phase 2: MUFU + smem stores
            float* ss = srow + (tile & 1) * (96 * SROW);
            #pragma unroll
            for (int c = 0; c < TILE; c++)
                ss[c] = conf * sig(v[c]);
        }
        __syncthreads();

        const int nfl = nrows * TILE;
        float* obase = sbase + tile * TILE;
        for (int j = (int)threadIdx.x * 4; j < nfl; j += 96 * 4) {
            int row = j >> 4;          // TILE = 16
            int col = j & 15;          // multiple of 4
            const float* sp = buf + row * SROW + col;
            *(float4*)(obase + (long)row * NC + col) =
                make_float4(sp[0], sp[1], sp[2], sp[3]);
        }
    }
}

extern "C" void kernel_launch(void* const* d_in, const int* in_sizes, int n_in,
                              void* d_out, int out_size) {
    (void)n_in; (void)out_size;
    const float* out0 = (const float*)d_in[0]; // [B, 258, 19, 19]
    const float* out1 = (const float*)d_in[1]; // [B, 258, 38, 38]
    const float* out2 = (const float*)d_in[2]; // [B, 258, 76, 76]
    const float* imsz = (const float*)d_in[3]; // [B, 2]
    float* o = (float*)d_out;

    const int B = in_sizes[3] / 2;
    yolo_fused<<<CHUNKS_TOT * B, 96>>>(out0, out1, out2, imsz, o, B);
}